// round 12
// baseline (speedup 1.0000x reference)
#include <cuda_runtime.h>
#include <cuda_fp16.h>
#include <cstdint>

// ============================================================================
// Fused geometric MLP trunk, fp16 mma.sync m16n8k16 (sm_100-plain).
//   rows = 524288, F=13(pad16), H=128, P=64
//   148 persistent CTAs x 320 threads (10 warps), 320-row tiles (last ragged),
//   32 rows/warp (mt=2). Paired B-fragment loads (LDS.128 -> 2 n-blocks).
//   Activations stay in registers between layers. Packed f32x2 epilogue math.
//   Layer-3 MMAs fused into the 2nd LN epilogue. Poly acos. Coords prefetch.
// ============================================================================

#define DEVINL static __device__ __forceinline__

DEVINL void mma_f16(float* d, const uint32_t* a, const uint32_t* b) {
    asm volatile(
        "mma.sync.aligned.m16n8k16.row.col.f32.f16.f16.f32 "
        "{%0,%1,%2,%3},{%4,%5,%6,%7},{%8,%9},{%0,%1,%2,%3};"
        : "+f"(d[0]), "+f"(d[1]), "+f"(d[2]), "+f"(d[3])
        : "r"(a[0]), "r"(a[1]), "r"(a[2]), "r"(a[3]), "r"(b[0]), "r"(b[1]));
}

// ---- packed f32x2 helpers (PTX ISA 8.6, sm_100 baseline) ----
DEVINL uint64_t pk2(float lo, float hi) {
    uint64_t r;
    asm("mov.b64 %0, {%1, %2};" : "=l"(r) : "f"(lo), "f"(hi));
    return r;
}
DEVINL void upk2(uint64_t v, float& lo, float& hi) {
    asm("mov.b64 {%0, %1}, %2;" : "=f"(lo), "=f"(hi) : "l"(v));
}
DEVINL uint64_t add2(uint64_t a, uint64_t b) {
    uint64_t r;
    asm("add.rn.f32x2 %0, %1, %2;" : "=l"(r) : "l"(a), "l"(b));
    return r;
}
DEVINL uint64_t fma2(uint64_t a, uint64_t b, uint64_t c) {
    uint64_t r;
    asm("fma.rn.f32x2 %0, %1, %2, %3;" : "=l"(r) : "l"(a), "l"(b), "l"(c));
    return r;
}
DEVINL uint32_t h2_from_pk(uint64_t y, __half2 hz) {
    float f0, f1;
    upk2(y, f0, f1);
    __half2 h = __hmax2(__floats2half2_rn(f0, f1), hz);
    return *reinterpret_cast<uint32_t*>(&h);
}

// acos via A&S 4.4.45: |err| <= 6.8e-5 rad; features are fp16-bound.
DEVINL float fast_acos(float x) {
    float ax = fabsf(x);
    float p = fmaf(fmaf(fmaf(-0.0187293f, ax, 0.0742610f), ax, -0.2121144f), ax, 1.5707288f);
    float s;
    asm("sqrt.approx.f32 %0, %1;" : "=f"(s) : "f"(1.0f - ax));
    float r = s * p;
    return x >= 0.f ? r : 3.14159265358979f - r;
}

// ---------------------------------------------------------------------------
static constexpr int TOTAL_ROWS = 32 * 16384;        // 524288
static constexpr int THREADS    = 320;               // 10 warps
static constexpr int TILE_ROWS  = 320;
static constexpr int TILES      = (TOTAL_ROWS + TILE_ROWS - 1) / TILE_ROWS;  // 1639
static constexpr float INV_PI   = 0.3183098861837907f;
static constexpr float INV_2PI  = 0.15915494309189535f;

// SMEM word (uint32) map
static constexpr int PB1 = 0, PG1 = 128, PBT1 = 256;
static constexpr int PB2 = 384, PG2 = 512, PBT2 = 640;
static constexpr int PB3 = 768;
static constexpr int PCRT = 832, PSRT = 848, PRP = 864;
static constexpr int W1F = 896;                 // 8 pairs  * 128 words = 1024
static constexpr int W2F = 1920;                // 64 pairs * 128 = 8192
static constexpr int W3F = 10112;               // 32 pairs * 128 = 4096
static constexpr int F2  = 14208;               // 320 rows * 8 half2-words = 2560
static constexpr int SMEM_WORDS = 16768;
static constexpr int SMEM_BYTES = SMEM_WORDS * 4;  // 67072

// Paired B packing for m16n8k16 f16 (B col-major K x N):
// pair covers n in [16np,16np+16): sub=0 -> cols 16np..+7, sub=1 -> +8..+15.
// lane l=(n&7)*4+((k>>1)&3) reads uint4 at (pair*128 + l*4):
//   .x/.y = b-frag words of block sub=0, .z/.w = block sub=1.
DEVINL void pack_pair(__half* hw, int base_words, int pair, int sub,
                      int kk, int nn, float v) {
    int lane = (nn << 2) | ((kk >> 1) & 3);
    int s    = kk >> 3;
    int pos  = kk & 1;
    hw[(base_words + pair * 128 + lane * 4 + sub * 2 + s) * 2 + pos] = __float2half_rn(v);
}

// LN stats for one 2-row fragment set (16 nt blocks): bias-add in place,
// return packed rs/beta for both rows.
DEVINL void ln_stats(float (*accm)[4], const float* bS, int tig,
                     uint64_t& rs0p, uint64_t& be0p, uint64_t& rs1p, uint64_t& be1p) {
    uint64_t sp00 = 0, sp01 = 0, qp00 = 0, qp01 = 0;   // row gid
    uint64_t sp10 = 0, sp11 = 0, qp10 = 0, qp11 = 0;   // row gid+8
#pragma unroll
    for (int nt = 0; nt < 16; nt++) {
        int c0 = 8 * nt + 2 * tig;
        uint64_t b01 = *reinterpret_cast<const uint64_t*>(bS + c0);
        uint64_t x01 = add2(pk2(accm[nt][0], accm[nt][1]), b01);
        uint64_t x23 = add2(pk2(accm[nt][2], accm[nt][3]), b01);
        upk2(x01, accm[nt][0], accm[nt][1]);
        upk2(x23, accm[nt][2], accm[nt][3]);
        if (nt & 1) {
            sp01 = add2(sp01, x01); qp01 = fma2(x01, x01, qp01);
            sp11 = add2(sp11, x23); qp11 = fma2(x23, x23, qp11);
        } else {
            sp00 = add2(sp00, x01); qp00 = fma2(x01, x01, qp00);
            sp10 = add2(sp10, x23); qp10 = fma2(x23, x23, qp10);
        }
    }
    float lo, hi;
    upk2(add2(sp00, sp01), lo, hi); float s0 = lo + hi;
    upk2(add2(qp00, qp01), lo, hi); float q0 = lo + hi;
    upk2(add2(sp10, sp11), lo, hi); float s1 = lo + hi;
    upk2(add2(qp10, qp11), lo, hi); float q1 = lo + hi;
    s0 += __shfl_xor_sync(0xffffffffu, s0, 1);
    s0 += __shfl_xor_sync(0xffffffffu, s0, 2);
    q0 += __shfl_xor_sync(0xffffffffu, q0, 1);
    q0 += __shfl_xor_sync(0xffffffffu, q0, 2);
    s1 += __shfl_xor_sync(0xffffffffu, s1, 1);
    s1 += __shfl_xor_sync(0xffffffffu, s1, 2);
    q1 += __shfl_xor_sync(0xffffffffu, q1, 1);
    q1 += __shfl_xor_sync(0xffffffffu, q1, 2);
    float mu0 = s0 * 0.0078125f;
    float mu1 = s1 * 0.0078125f;
    float rs0 = rsqrtf(fmaf(-mu0, mu0, q0 * 0.0078125f) + 1e-5f);
    float rs1 = rsqrtf(fmaf(-mu1, mu1, q1 * 0.0078125f) + 1e-5f);
    rs0p = pk2(rs0, rs0); be0p = pk2(-mu0 * rs0, -mu0 * rs0);
    rs1p = pk2(rs1, rs1); be1p = pk2(-mu1 * rs1, -mu1 * rs1);
}

// Normalize + relu + fp16-pack the 4 A-frag words for one kt.
DEVINL void pack_kt(float (*accm)[4], int kt, int tig,
                    const float* gS, const float* tS,
                    uint64_t rs0p, uint64_t be0p, uint64_t rs1p, uint64_t be1p,
                    __half2 hz, uint32_t* frag) {
    int cA = 16 * kt + 2 * tig;
    int cB = cA + 8;
    uint64_t gA = *reinterpret_cast<const uint64_t*>(gS + cA);
    uint64_t tA = *reinterpret_cast<const uint64_t*>(tS + cA);
    uint64_t gB = *reinterpret_cast<const uint64_t*>(gS + cB);
    uint64_t tB = *reinterpret_cast<const uint64_t*>(tS + cB);
    frag[0] = h2_from_pk(fma2(fma2(pk2(accm[2*kt][0],   accm[2*kt][1]),   rs0p, be0p), gA, tA), hz);
    frag[1] = h2_from_pk(fma2(fma2(pk2(accm[2*kt][2],   accm[2*kt][3]),   rs1p, be1p), gA, tA), hz);
    frag[2] = h2_from_pk(fma2(fma2(pk2(accm[2*kt+1][0], accm[2*kt+1][1]), rs0p, be0p), gB, tB), hz);
    frag[3] = h2_from_pk(fma2(fma2(pk2(accm[2*kt+1][2], accm[2*kt+1][3]), rs1p, be1p), gB, tB), hz);
}

__global__ void __launch_bounds__(THREADS, 1)
geo_trunk_kernel(const float* __restrict__ coords,
                 const float* __restrict__ ref_theta, const float* __restrict__ ref_phi,
                 const float* __restrict__ W1, const float* __restrict__ b1,
                 const float* __restrict__ g1, const float* __restrict__ bt1,
                 const float* __restrict__ W2, const float* __restrict__ b2,
                 const float* __restrict__ g2, const float* __restrict__ bt2,
                 const float* __restrict__ W3, const float* __restrict__ b3,
                 float* __restrict__ out) {
    extern __shared__ float sf[];
    uint32_t* su = reinterpret_cast<uint32_t*>(sf);
    __half*   hw = reinterpret_cast<__half*>(sf);

    const int tid  = threadIdx.x;
    const int lane = tid & 31;
    const int gid  = lane >> 2;
    const int tig  = lane & 3;
    const int wrow = (tid >> 5) * 32;   // CTA-local row base of this warp

    // ---- one-time setup ----
    for (int t = tid; t < 16 * 128; t += THREADS) {    // W1 (zero-pad k>=13)
        int k = t >> 7, n = t & 127;
        pack_pair(hw, W1F, n >> 4, (n >> 3) & 1, k & 15, n & 7,
                  k < 13 ? W1[k * 128 + n] : 0.0f);
    }
    for (int t = tid; t < 128 * 128; t += THREADS) {   // W2
        int k = t >> 7, n = t & 127;
        pack_pair(hw, W2F, (k >> 4) * 8 + (n >> 4), (n >> 3) & 1, k & 15, n & 7, W2[t]);
    }
    for (int t = tid; t < 128 * 64; t += THREADS) {    // W3
        int k = t >> 6, n = t & 63;
        pack_pair(hw, W3F, (k >> 4) * 4 + (n >> 4), (n >> 3) & 1, k & 15, n & 7, W3[t]);
    }
    if (tid < 128) {
        sf[PB1 + tid]  = b1[tid];
        sf[PG1 + tid]  = g1[tid];
        sf[PBT1 + tid] = bt1[tid];
        sf[PB2 + tid]  = b2[tid];
        sf[PG2 + tid]  = g2[tid];
        sf[PBT2 + tid] = bt2[tid];
        if (tid < 64) sf[PB3 + tid] = b3[tid];
        if (tid < 10) {
            float rt = ref_theta[tid];
            sf[PCRT + tid] = cosf(rt);
            sf[PSRT + tid] = sinf(rt);
            sf[PRP + tid]  = ref_phi[tid];
        }
    }
    __syncthreads();

    const float* bS1 = sf + PB1; const float* gS1 = sf + PG1; const float* tS1 = sf + PBT1;
    const float* bS2 = sf + PB2; const float* gS2 = sf + PG2; const float* tS2 = sf + PBT2;
    const float* bS3 = sf + PB3;
    const float* crt = sf + PCRT; const float* srt = sf + PSRT; const float* rp = sf + PRP;
    const float2* coords2 = reinterpret_cast<const float2*>(coords);
    const __half2 hz = __float2half2_rn(0.f);

    // prefetch first tile's coords (clamped for ragged last tile)
    float2 tp;
    {
        int r = blockIdx.x * TILE_ROWS + tid;
        tp = coords2[r < TOTAL_ROWS ? r : TOTAL_ROWS - 1];
    }

    for (int tile = blockIdx.x; tile < TILES; tile += gridDim.x) {
        // ============== features: 1 row / thread ==============
        {
            float th = tp.x, ph = tp.y;
            float st, ct;
            __sincosf(th, &st, &ct);
            float f[16];
#pragma unroll
            for (int r = 0; r < 10; r++) {
                float cd = fmaf(st * srt[r], __cosf(ph - rp[r]), ct * crt[r]);
                cd = fminf(1.0f, fmaxf(-1.0f, cd));
                f[r] = fast_acos(cd) * INV_PI;
            }
            f[10] = th * INV_PI;
            f[11] = ph * INV_2PI;
            f[12] = 1.0f;
            f[13] = 0.f; f[14] = 0.f; f[15] = 0.f;
            const int sw = ((tid >> 2) & 1) << 2;  // feat swizzle bit
#pragma unroll
            for (int i = 0; i < 8; i++) {
                __half2 h = __floats2half2_rn(f[2 * i], f[2 * i + 1]);
                su[F2 + tid * 8 + (i ^ sw)] = *reinterpret_cast<uint32_t*>(&h);
            }
        }
        // prefetch next tile's coords (flies under the MMA phases)
        {
            int ntile = tile + gridDim.x;
            if (ntile < TILES) {
                int r = ntile * TILE_ROWS + tid;
                tp = coords2[r < TOTAL_ROWS ? r : TOTAL_ROWS - 1];
            }
        }
        __syncwarp();

        float    acc[2][16][4];
        uint32_t ha[2][8][4];   // activation A-fragments (layer1 -> layer2)

        // ============== layer 1: feats @ W1 (1 k-step) ==============
#pragma unroll
        for (int mt = 0; mt < 2; mt++)
#pragma unroll
            for (int nt = 0; nt < 16; nt++)
#pragma unroll
                for (int e = 0; e < 4; e++) acc[mt][nt][e] = 0.f;
        {
            uint32_t a[2][4];
#pragma unroll
            for (int mt = 0; mt < 2; mt++) {
                int r0 = wrow + mt * 16 + gid;
                int s0 = ((r0 >> 2) & 1) << 2;
                a[mt][0] = su[F2 + r0 * 8       + (tig ^ s0)];
                a[mt][1] = su[F2 + (r0 + 8) * 8 + (tig ^ s0)];
                a[mt][2] = su[F2 + r0 * 8       + ((tig + 4) ^ s0)];
                a[mt][3] = su[F2 + (r0 + 8) * 8 + ((tig + 4) ^ s0)];
            }
#pragma unroll
            for (int p = 0; p < 8; p++) {
                uint4 bv = *reinterpret_cast<const uint4*>(su + W1F + p * 128 + lane * 4);
                uint32_t b0[2] = {bv.x, bv.y};
                uint32_t b1v[2] = {bv.z, bv.w};
                mma_f16(acc[0][2 * p],     a[0], b0);
                mma_f16(acc[1][2 * p],     a[1], b0);
                mma_f16(acc[0][2 * p + 1], a[0], b1v);
                mma_f16(acc[1][2 * p + 1], a[1], b1v);
            }
        }

        // ============== LN1 epilogue -> ha ==============
        {
            uint64_t rs0p, be0p, rs1p, be1p;
#pragma unroll
            for (int mt = 0; mt < 2; mt++) {
                ln_stats(acc[mt], bS1, tig, rs0p, be0p, rs1p, be1p);
#pragma unroll
                for (int kt = 0; kt < 8; kt++)
                    pack_kt(acc[mt], kt, tig, gS1, tS1, rs0p, be0p, rs1p, be1p, hz, ha[mt][kt]);
            }
        }

        // ============== layer 2: h1 @ W2 (8 k-steps, paired loads) ==============
#pragma unroll
        for (int mt = 0; mt < 2; mt++)
#pragma unroll
            for (int nt = 0; nt < 16; nt++)
#pragma unroll
                for (int e = 0; e < 4; e++) acc[mt][nt][e] = 0.f;
#pragma unroll
        for (int kt = 0; kt < 8; kt++) {
#pragma unroll
            for (int p = 0; p < 8; p++) {
                uint4 bv = *reinterpret_cast<const uint4*>(su + W2F + (kt * 8 + p) * 128 + lane * 4);
                uint32_t b0[2] = {bv.x, bv.y};
                uint32_t b1v[2] = {bv.z, bv.w};
                mma_f16(acc[0][2 * p],     ha[0][kt], b0);
                mma_f16(acc[1][2 * p],     ha[1][kt], b0);
                mma_f16(acc[0][2 * p + 1], ha[0][kt], b1v);
                mma_f16(acc[1][2 * p + 1], ha[1][kt], b1v);
            }
        }

        // ============== LN2 epilogue FUSED with layer 3 ==============
        float a3[2][8][4];
#pragma unroll
        for (int mt = 0; mt < 2; mt++)
#pragma unroll
            for (int nt = 0; nt < 8; nt++)
#pragma unroll
                for (int e = 0; e < 4; e++) a3[mt][nt][e] = 0.f;
        {
            uint64_t rs0p0, be0p0, rs1p0, be1p0;
            uint64_t rs0p1, be0p1, rs1p1, be1p1;
            ln_stats(acc[0], bS2, tig, rs0p0, be0p0, rs1p0, be1p0);
            ln_stats(acc[1], bS2, tig, rs0p1, be0p1, rs1p1, be1p1);
#pragma unroll
            for (int kt = 0; kt < 8; kt++) {
                uint32_t hb0[4], hb1[4];
                pack_kt(acc[0], kt, tig, gS2, tS2, rs0p0, be0p0, rs1p0, be1p0, hz, hb0);
                pack_kt(acc[1], kt, tig, gS2, tS2, rs0p1, be0p1, rs1p1, be1p1, hz, hb1);
#pragma unroll
                for (int p = 0; p < 4; p++) {
                    uint4 bv = *reinterpret_cast<const uint4*>(su + W3F + (kt * 4 + p) * 128 + lane * 4);
                    uint32_t b0[2] = {bv.x, bv.y};
                    uint32_t b1v[2] = {bv.z, bv.w};
                    mma_f16(a3[0][2 * p],     hb0, b0);
                    mma_f16(a3[1][2 * p],     hb1, b0);
                    mma_f16(a3[0][2 * p + 1], hb0, b1v);
                    mma_f16(a3[1][2 * p + 1], hb1, b1v);
                }
            }
        }

        // ============== bias + store (guarded for ragged last tile) ==============
        {
            const int rowg = tile * TILE_ROWS + wrow;
#pragma unroll
            for (int mt = 0; mt < 2; mt++) {
                int r0 = rowg + mt * 16 + gid, r1 = r0 + 8;
#pragma unroll
                for (int nt = 0; nt < 8; nt++) {
                    int c0 = 8 * nt + 2 * tig;
                    uint64_t b01 = *reinterpret_cast<const uint64_t*>(bS3 + c0);
                    uint64_t v0 = add2(pk2(a3[mt][nt][0], a3[mt][nt][1]), b01);
                    uint64_t v1 = add2(pk2(a3[mt][nt][2], a3[mt][nt][3]), b01);
                    if (r0 < TOTAL_ROWS)
                        *reinterpret_cast<uint64_t*>(out + (size_t)r0 * 64 + c0) = v0;
                    if (r1 < TOTAL_ROWS)
                        *reinterpret_cast<uint64_t*>(out + (size_t)r1 * 64 + c0) = v1;
                }
            }
        }
    }
}

extern "C" void kernel_launch(void* const* d_in, const int* in_sizes, int n_in,
                              void* d_out, int out_size) {
    (void)in_sizes; (void)n_in; (void)out_size;
    cudaFuncSetAttribute(geo_trunk_kernel, cudaFuncAttributeMaxDynamicSharedMemorySize, SMEM_BYTES);
    geo_trunk_kernel<<<148, THREADS, SMEM_BYTES>>>(
        (const float*)d_in[0],  // coords
        (const float*)d_in[1],  // ref_theta
        (const float*)d_in[2],  // ref_phi
        (const float*)d_in[3],  // W1
        (const float*)d_in[4],  // b1
        (const float*)d_in[5],  // g1
        (const float*)d_in[6],  // bt1
        (const float*)d_in[7],  // W2
        (const float*)d_in[8],  // b2
        (const float*)d_in[9],  // g2
        (const float*)d_in[10], // bt2
        (const float*)d_in[11], // W3
        (const float*)d_in[12], // b3
        (float*)d_out);
}

// round 13
// speedup vs baseline: 1.2075x; 1.2075x over previous
#include <cuda_runtime.h>
#include <cuda_fp16.h>
#include <cstdint>

// ============================================================================
// Fused geometric MLP trunk, fp16 mma.sync m16n8k16 (sm_100-plain).
//   rows = 524288, F=13(pad16), H=128, P=64
//   148 persistent CTAs x 256 threads, 256-row tiles, 32 rows/warp (mt=2).
//   Paired B-fragment loads (LDS.128 -> 2 n-blocks). Activations stay in
//   registers between layers. Packed f32x2 epilogue math. Layer-3 MMAs fused
//   into the 2nd LN epilogue. Poly acos. Coords prefetched 1 tile.
//   R13: LN1's two ln_stats chains issued back-to-back (shuffles overlap).
// ============================================================================

#define DEVINL static __device__ __forceinline__

DEVINL void mma_f16(float* d, const uint32_t* a, const uint32_t* b) {
    asm volatile(
        "mma.sync.aligned.m16n8k16.row.col.f32.f16.f16.f32 "
        "{%0,%1,%2,%3},{%4,%5,%6,%7},{%8,%9},{%0,%1,%2,%3};"
        : "+f"(d[0]), "+f"(d[1]), "+f"(d[2]), "+f"(d[3])
        : "r"(a[0]), "r"(a[1]), "r"(a[2]), "r"(a[3]), "r"(b[0]), "r"(b[1]));
}

// ---- packed f32x2 helpers (PTX ISA 8.6, sm_100 baseline) ----
DEVINL uint64_t pk2(float lo, float hi) {
    uint64_t r;
    asm("mov.b64 %0, {%1, %2};" : "=l"(r) : "f"(lo), "f"(hi));
    return r;
}
DEVINL void upk2(uint64_t v, float& lo, float& hi) {
    asm("mov.b64 {%0, %1}, %2;" : "=f"(lo), "=f"(hi) : "l"(v));
}
DEVINL uint64_t add2(uint64_t a, uint64_t b) {
    uint64_t r;
    asm("add.rn.f32x2 %0, %1, %2;" : "=l"(r) : "l"(a), "l"(b));
    return r;
}
DEVINL uint64_t fma2(uint64_t a, uint64_t b, uint64_t c) {
    uint64_t r;
    asm("fma.rn.f32x2 %0, %1, %2, %3;" : "=l"(r) : "l"(a), "l"(b), "l"(c));
    return r;
}
DEVINL uint32_t h2_from_pk(uint64_t y, __half2 hz) {
    float f0, f1;
    upk2(y, f0, f1);
    __half2 h = __hmax2(__floats2half2_rn(f0, f1), hz);
    return *reinterpret_cast<uint32_t*>(&h);
}

// acos via A&S 4.4.45: |err| <= 6.8e-5 rad; features are fp16-bound.
DEVINL float fast_acos(float x) {
    float ax = fabsf(x);
    float p = fmaf(fmaf(fmaf(-0.0187293f, ax, 0.0742610f), ax, -0.2121144f), ax, 1.5707288f);
    float s;
    asm("sqrt.approx.f32 %0, %1;" : "=f"(s) : "f"(1.0f - ax));
    float r = s * p;
    return x >= 0.f ? r : 3.14159265358979f - r;
}

// ---------------------------------------------------------------------------
static constexpr int TOTAL_ROWS = 32 * 16384;        // 524288
static constexpr int TILE_ROWS  = 256;
static constexpr int TILES      = TOTAL_ROWS / TILE_ROWS;  // 2048
static constexpr float INV_PI   = 0.3183098861837907f;
static constexpr float INV_2PI  = 0.15915494309189535f;

// SMEM word (uint32) map
static constexpr int PB1 = 0, PG1 = 128, PBT1 = 256;
static constexpr int PB2 = 384, PG2 = 512, PBT2 = 640;
static constexpr int PB3 = 768;
static constexpr int PCRT = 832, PSRT = 848, PRP = 864;
static constexpr int W1F = 896;                 // 8 pairs  * 128 words = 1024
static constexpr int W2F = 1920;                // 64 pairs * 128 = 8192
static constexpr int W3F = 10112;               // 32 pairs * 128 = 4096
static constexpr int F2  = 14208;               // 256 rows * 8 half2-words = 2048
static constexpr int SMEM_WORDS = 16256;
static constexpr int SMEM_BYTES = SMEM_WORDS * 4;  // 65024

// Paired B packing for m16n8k16 f16 (B col-major K x N):
// pair covers n in [16np,16np+16): sub=0 -> cols 16np..+7, sub=1 -> +8..+15.
// lane l=(n&7)*4+((k>>1)&3) reads uint4 at (pair*128 + l*4):
//   .x/.y = b-frag words of block sub=0, .z/.w = block sub=1.
DEVINL void pack_pair(__half* hw, int base_words, int pair, int sub,
                      int kk, int nn, float v) {
    int lane = (nn << 2) | ((kk >> 1) & 3);
    int s    = kk >> 3;
    int pos  = kk & 1;
    hw[(base_words + pair * 128 + lane * 4 + sub * 2 + s) * 2 + pos] = __float2half_rn(v);
}

// LN stats for one 2-row fragment set (16 nt blocks): bias-add in place,
// return packed rs/beta for both rows.
DEVINL void ln_stats(float (*accm)[4], const float* bS, int tig,
                     uint64_t& rs0p, uint64_t& be0p, uint64_t& rs1p, uint64_t& be1p) {
    uint64_t sp00 = 0, sp01 = 0, qp00 = 0, qp01 = 0;   // row gid
    uint64_t sp10 = 0, sp11 = 0, qp10 = 0, qp11 = 0;   // row gid+8
#pragma unroll
    for (int nt = 0; nt < 16; nt++) {
        int c0 = 8 * nt + 2 * tig;
        uint64_t b01 = *reinterpret_cast<const uint64_t*>(bS + c0);
        uint64_t x01 = add2(pk2(accm[nt][0], accm[nt][1]), b01);
        uint64_t x23 = add2(pk2(accm[nt][2], accm[nt][3]), b01);
        upk2(x01, accm[nt][0], accm[nt][1]);
        upk2(x23, accm[nt][2], accm[nt][3]);
        if (nt & 1) {
            sp01 = add2(sp01, x01); qp01 = fma2(x01, x01, qp01);
            sp11 = add2(sp11, x23); qp11 = fma2(x23, x23, qp11);
        } else {
            sp00 = add2(sp00, x01); qp00 = fma2(x01, x01, qp00);
            sp10 = add2(sp10, x23); qp10 = fma2(x23, x23, qp10);
        }
    }
    float lo, hi;
    upk2(add2(sp00, sp01), lo, hi); float s0 = lo + hi;
    upk2(add2(qp00, qp01), lo, hi); float q0 = lo + hi;
    upk2(add2(sp10, sp11), lo, hi); float s1 = lo + hi;
    upk2(add2(qp10, qp11), lo, hi); float q1 = lo + hi;
    s0 += __shfl_xor_sync(0xffffffffu, s0, 1);
    s0 += __shfl_xor_sync(0xffffffffu, s0, 2);
    q0 += __shfl_xor_sync(0xffffffffu, q0, 1);
    q0 += __shfl_xor_sync(0xffffffffu, q0, 2);
    s1 += __shfl_xor_sync(0xffffffffu, s1, 1);
    s1 += __shfl_xor_sync(0xffffffffu, s1, 2);
    q1 += __shfl_xor_sync(0xffffffffu, q1, 1);
    q1 += __shfl_xor_sync(0xffffffffu, q1, 2);
    float mu0 = s0 * 0.0078125f;
    float mu1 = s1 * 0.0078125f;
    float rs0 = rsqrtf(fmaf(-mu0, mu0, q0 * 0.0078125f) + 1e-5f);
    float rs1 = rsqrtf(fmaf(-mu1, mu1, q1 * 0.0078125f) + 1e-5f);
    rs0p = pk2(rs0, rs0); be0p = pk2(-mu0 * rs0, -mu0 * rs0);
    rs1p = pk2(rs1, rs1); be1p = pk2(-mu1 * rs1, -mu1 * rs1);
}

// Normalize + relu + fp16-pack the 4 A-frag words for one kt.
DEVINL void pack_kt(float (*accm)[4], int kt, int tig,
                    const float* gS, const float* tS,
                    uint64_t rs0p, uint64_t be0p, uint64_t rs1p, uint64_t be1p,
                    __half2 hz, uint32_t* frag) {
    int cA = 16 * kt + 2 * tig;
    int cB = cA + 8;
    uint64_t gA = *reinterpret_cast<const uint64_t*>(gS + cA);
    uint64_t tA = *reinterpret_cast<const uint64_t*>(tS + cA);
    uint64_t gB = *reinterpret_cast<const uint64_t*>(gS + cB);
    uint64_t tB = *reinterpret_cast<const uint64_t*>(tS + cB);
    frag[0] = h2_from_pk(fma2(fma2(pk2(accm[2*kt][0],   accm[2*kt][1]),   rs0p, be0p), gA, tA), hz);
    frag[1] = h2_from_pk(fma2(fma2(pk2(accm[2*kt][2],   accm[2*kt][3]),   rs1p, be1p), gA, tA), hz);
    frag[2] = h2_from_pk(fma2(fma2(pk2(accm[2*kt+1][0], accm[2*kt+1][1]), rs0p, be0p), gB, tB), hz);
    frag[3] = h2_from_pk(fma2(fma2(pk2(accm[2*kt+1][2], accm[2*kt+1][3]), rs1p, be1p), gB, tB), hz);
}

__global__ void __launch_bounds__(256, 1)
geo_trunk_kernel(const float* __restrict__ coords,
                 const float* __restrict__ ref_theta, const float* __restrict__ ref_phi,
                 const float* __restrict__ W1, const float* __restrict__ b1,
                 const float* __restrict__ g1, const float* __restrict__ bt1,
                 const float* __restrict__ W2, const float* __restrict__ b2,
                 const float* __restrict__ g2, const float* __restrict__ bt2,
                 const float* __restrict__ W3, const float* __restrict__ b3,
                 float* __restrict__ out) {
    extern __shared__ float sf[];
    uint32_t* su = reinterpret_cast<uint32_t*>(sf);
    __half*   hw = reinterpret_cast<__half*>(sf);

    const int tid  = threadIdx.x;
    const int lane = tid & 31;
    const int gid  = lane >> 2;
    const int tig  = lane & 3;
    const int wrow = (tid >> 5) * 32;   // CTA-local row base of this warp

    // ---- one-time setup ----
    for (int t = tid; t < 16 * 128; t += 256) {        // W1 (zero-pad k>=13)
        int k = t >> 7, n = t & 127;
        pack_pair(hw, W1F, n >> 4, (n >> 3) & 1, k & 15, n & 7,
                  k < 13 ? W1[k * 128 + n] : 0.0f);
    }
    for (int t = tid; t < 128 * 128; t += 256) {       // W2
        int k = t >> 7, n = t & 127;
        pack_pair(hw, W2F, (k >> 4) * 8 + (n >> 4), (n >> 3) & 1, k & 15, n & 7, W2[t]);
    }
    for (int t = tid; t < 128 * 64; t += 256) {        // W3
        int k = t >> 6, n = t & 63;
        pack_pair(hw, W3F, (k >> 4) * 4 + (n >> 4), (n >> 3) & 1, k & 15, n & 7, W3[t]);
    }
    if (tid < 128) {
        sf[PB1 + tid]  = b1[tid];
        sf[PG1 + tid]  = g1[tid];
        sf[PBT1 + tid] = bt1[tid];
        sf[PB2 + tid]  = b2[tid];
        sf[PG2 + tid]  = g2[tid];
        sf[PBT2 + tid] = bt2[tid];
        if (tid < 64) sf[PB3 + tid] = b3[tid];
        if (tid < 10) {
            float rt = ref_theta[tid];
            sf[PCRT + tid] = cosf(rt);
            sf[PSRT + tid] = sinf(rt);
            sf[PRP + tid]  = ref_phi[tid];
        }
    }
    __syncthreads();

    const float* bS1 = sf + PB1; const float* gS1 = sf + PG1; const float* tS1 = sf + PBT1;
    const float* bS2 = sf + PB2; const float* gS2 = sf + PG2; const float* tS2 = sf + PBT2;
    const float* bS3 = sf + PB3;
    const float* crt = sf + PCRT; const float* srt = sf + PSRT; const float* rp = sf + PRP;
    const float2* coords2 = reinterpret_cast<const float2*>(coords);
    const __half2 hz = __float2half2_rn(0.f);

    // prefetch first tile's coords
    float2 tp = coords2[blockIdx.x * TILE_ROWS + tid];

    for (int tile = blockIdx.x; tile < TILES; tile += gridDim.x) {
        // ============== features: 1 row / thread ==============
        {
            float th = tp.x, ph = tp.y;
            float st, ct;
            __sincosf(th, &st, &ct);
            float f[16];
#pragma unroll
            for (int r = 0; r < 10; r++) {
                float cd = fmaf(st * srt[r], __cosf(ph - rp[r]), ct * crt[r]);
                cd = fminf(1.0f, fmaxf(-1.0f, cd));
                f[r] = fast_acos(cd) * INV_PI;
            }
            f[10] = th * INV_PI;
            f[11] = ph * INV_2PI;
            f[12] = 1.0f;
            f[13] = 0.f; f[14] = 0.f; f[15] = 0.f;
            const int sw = ((tid >> 2) & 1) << 2;  // feat swizzle bit
#pragma unroll
            for (int i = 0; i < 8; i++) {
                __half2 h = __floats2half2_rn(f[2 * i], f[2 * i + 1]);
                su[F2 + tid * 8 + (i ^ sw)] = *reinterpret_cast<uint32_t*>(&h);
            }
        }
        // prefetch next tile's coords (flies under the MMA phases)
        {
            int ntile = tile + gridDim.x;
            if (ntile < TILES) tp = coords2[ntile * TILE_ROWS + tid];
        }
        __syncwarp();

        float    acc[2][16][4];
        uint32_t ha[2][8][4];   // activation A-fragments (layer1 -> layer2)

        // ============== layer 1: feats[256x16] @ W1 (1 k-step) ==============
#pragma unroll
        for (int mt = 0; mt < 2; mt++)
#pragma unroll
            for (int nt = 0; nt < 16; nt++)
#pragma unroll
                for (int e = 0; e < 4; e++) acc[mt][nt][e] = 0.f;
        {
            uint32_t a[2][4];
#pragma unroll
            for (int mt = 0; mt < 2; mt++) {
                int r0 = wrow + mt * 16 + gid;
                int s0 = ((r0 >> 2) & 1) << 2;
                a[mt][0] = su[F2 + r0 * 8       + (tig ^ s0)];
                a[mt][1] = su[F2 + (r0 + 8) * 8 + (tig ^ s0)];
                a[mt][2] = su[F2 + r0 * 8       + ((tig + 4) ^ s0)];
                a[mt][3] = su[F2 + (r0 + 8) * 8 + ((tig + 4) ^ s0)];
            }
#pragma unroll
            for (int p = 0; p < 8; p++) {
                uint4 bv = *reinterpret_cast<const uint4*>(su + W1F + p * 128 + lane * 4);
                uint32_t b0[2] = {bv.x, bv.y};
                uint32_t b1v[2] = {bv.z, bv.w};
                mma_f16(acc[0][2 * p],     a[0], b0);
                mma_f16(acc[1][2 * p],     a[1], b0);
                mma_f16(acc[0][2 * p + 1], a[0], b1v);
                mma_f16(acc[1][2 * p + 1], a[1], b1v);
            }
        }

        // ============== LN1 epilogue -> ha (both stats chains overlap) ==============
        {
            uint64_t rs0p0, be0p0, rs1p0, be1p0;
            uint64_t rs0p1, be0p1, rs1p1, be1p1;
            ln_stats(acc[0], bS1, tig, rs0p0, be0p0, rs1p0, be1p0);
            ln_stats(acc[1], bS1, tig, rs0p1, be0p1, rs1p1, be1p1);
#pragma unroll
            for (int kt = 0; kt < 8; kt++) {
                pack_kt(acc[0], kt, tig, gS1, tS1, rs0p0, be0p0, rs1p0, be1p0, hz, ha[0][kt]);
                pack_kt(acc[1], kt, tig, gS1, tS1, rs0p1, be0p1, rs1p1, be1p1, hz, ha[1][kt]);
            }
        }

        // ============== layer 2: h1 @ W2 (8 k-steps, paired loads) ==============
#pragma unroll
        for (int mt = 0; mt < 2; mt++)
#pragma unroll
            for (int nt = 0; nt < 16; nt++)
#pragma unroll
                for (int e = 0; e < 4; e++) acc[mt][nt][e] = 0.f;
#pragma unroll
        for (int kt = 0; kt < 8; kt++) {
#pragma unroll
            for (int p = 0; p < 8; p++) {
                uint4 bv = *reinterpret_cast<const uint4*>(su + W2F + (kt * 8 + p) * 128 + lane * 4);
                uint32_t b0[2] = {bv.x, bv.y};
                uint32_t b1v[2] = {bv.z, bv.w};
                mma_f16(acc[0][2 * p],     ha[0][kt], b0);
                mma_f16(acc[1][2 * p],     ha[1][kt], b0);
                mma_f16(acc[0][2 * p + 1], ha[0][kt], b1v);
                mma_f16(acc[1][2 * p + 1], ha[1][kt], b1v);
            }
        }

        // ============== LN2 epilogue FUSED with layer 3 ==============
        float a3[2][8][4];
#pragma unroll
        for (int mt = 0; mt < 2; mt++)
#pragma unroll
            for (int nt = 0; nt < 8; nt++)
#pragma unroll
                for (int e = 0; e < 4; e++) a3[mt][nt][e] = 0.f;
        {
            uint64_t rs0p0, be0p0, rs1p0, be1p0;
            uint64_t rs0p1, be0p1, rs1p1, be1p1;
            ln_stats(acc[0], bS2, tig, rs0p0, be0p0, rs1p0, be1p0);
            ln_stats(acc[1], bS2, tig, rs0p1, be0p1, rs1p1, be1p1);
#pragma unroll
            for (int kt = 0; kt < 8; kt++) {
                uint32_t hb0[4], hb1[4];
                pack_kt(acc[0], kt, tig, gS2, tS2, rs0p0, be0p0, rs1p0, be1p0, hz, hb0);
                pack_kt(acc[1], kt, tig, gS2, tS2, rs0p1, be0p1, rs1p1, be1p1, hz, hb1);
#pragma unroll
                for (int p = 0; p < 4; p++) {
                    uint4 bv = *reinterpret_cast<const uint4*>(su + W3F + (kt * 4 + p) * 128 + lane * 4);
                    uint32_t b0[2] = {bv.x, bv.y};
                    uint32_t b1v[2] = {bv.z, bv.w};
                    mma_f16(a3[0][2 * p],     hb0, b0);
                    mma_f16(a3[1][2 * p],     hb1, b0);
                    mma_f16(a3[0][2 * p + 1], hb0, b1v);
                    mma_f16(a3[1][2 * p + 1], hb1, b1v);
                }
            }
        }

        // ============== bias + store ==============
        {
            const int rowg = tile * TILE_ROWS + wrow;
#pragma unroll
            for (int mt = 0; mt < 2; mt++) {
                int r0 = rowg + mt * 16 + gid, r1 = r0 + 8;
#pragma unroll
                for (int nt = 0; nt < 8; nt++) {
                    int c0 = 8 * nt + 2 * tig;
                    uint64_t b01 = *reinterpret_cast<const uint64_t*>(bS3 + c0);
                    uint64_t v0 = add2(pk2(a3[mt][nt][0], a3[mt][nt][1]), b01);
                    uint64_t v1 = add2(pk2(a3[mt][nt][2], a3[mt][nt][3]), b01);
                    *reinterpret_cast<uint64_t*>(out + (size_t)r0 * 64 + c0) = v0;
                    *reinterpret_cast<uint64_t*>(out + (size_t)r1 * 64 + c0) = v1;
                }
            }
        }
    }
}

extern "C" void kernel_launch(void* const* d_in, const int* in_sizes, int n_in,
                              void* d_out, int out_size) {
    (void)in_sizes; (void)n_in; (void)out_size;
    cudaFuncSetAttribute(geo_trunk_kernel, cudaFuncAttributeMaxDynamicSharedMemorySize, SMEM_BYTES);
    geo_trunk_kernel<<<148, 256, SMEM_BYTES>>>(
        (const float*)d_in[0],  // coords
        (const float*)d_in[1],  // ref_theta
        (const float*)d_in[2],  // ref_phi
        (const float*)d_in[3],  // W1
        (const float*)d_in[4],  // b1
        (const float*)d_in[5],  // g1
        (const float*)d_in[6],  // bt1
        (const float*)d_in[7],  // W2
        (const float*)d_in[8],  // b2
        (const float*)d_in[9],  // g2
        (const float*)d_in[10], // bt2
        (const float*)d_in[11], // W3
        (const float*)d_in[12], // b3
        (float*)d_out);
}

// round 14
// speedup vs baseline: 1.2219x; 1.0119x over previous
#include <cuda_runtime.h>
#include <cuda_fp16.h>
#include <cstdint>

// ============================================================================
// Fused geometric MLP trunk, fp16 mma.sync m16n8k16 (sm_100-plain).
//   rows = 524288, F=13(pad16), H=128, P=64
//   148 persistent CTAs x 256 threads, 256-row tiles, 32 rows/warp (mt=2).
//   Paired B-fragment loads (LDS.128 -> 2 n-blocks). Activations stay in
//   registers between layers. Packed f32x2 epilogue math. Layer-3 MMAs fused
//   into the 2nd LN epilogue. Poly acos. Coords prefetched 1 tile.
//   R14: biases folded into the MMA C-operand (no zero-init, no bias add);
//        gamma/beta interleaved for LDS.128 epilogue loads.
// ============================================================================

#define DEVINL static __device__ __forceinline__

DEVINL void mma_f16(float* d, const uint32_t* a, const uint32_t* b) {
    asm volatile(
        "mma.sync.aligned.m16n8k16.row.col.f32.f16.f16.f32 "
        "{%0,%1,%2,%3},{%4,%5,%6,%7},{%8,%9},{%0,%1,%2,%3};"
        : "+f"(d[0]), "+f"(d[1]), "+f"(d[2]), "+f"(d[3])
        : "r"(a[0]), "r"(a[1]), "r"(a[2]), "r"(a[3]), "r"(b[0]), "r"(b[1]));
}

// ---- packed f32x2 helpers (PTX ISA 8.6, sm_100 baseline) ----
DEVINL uint64_t pk2(float lo, float hi) {
    uint64_t r;
    asm("mov.b64 %0, {%1, %2};" : "=l"(r) : "f"(lo), "f"(hi));
    return r;
}
DEVINL void upk2(uint64_t v, float& lo, float& hi) {
    asm("mov.b64 {%0, %1}, %2;" : "=f"(lo), "=f"(hi) : "l"(v));
}
DEVINL uint64_t add2(uint64_t a, uint64_t b) {
    uint64_t r;
    asm("add.rn.f32x2 %0, %1, %2;" : "=l"(r) : "l"(a), "l"(b));
    return r;
}
DEVINL uint64_t fma2(uint64_t a, uint64_t b, uint64_t c) {
    uint64_t r;
    asm("fma.rn.f32x2 %0, %1, %2, %3;" : "=l"(r) : "l"(a), "l"(b), "l"(c));
    return r;
}
DEVINL uint32_t h2_from_pk(uint64_t y, __half2 hz) {
    float f0, f1;
    upk2(y, f0, f1);
    __half2 h = __hmax2(__floats2half2_rn(f0, f1), hz);
    return *reinterpret_cast<uint32_t*>(&h);
}

// acos via A&S 4.4.45: |err| <= 6.8e-5 rad; features are fp16-bound.
DEVINL float fast_acos(float x) {
    float ax = fabsf(x);
    float p = fmaf(fmaf(fmaf(-0.0187293f, ax, 0.0742610f), ax, -0.2121144f), ax, 1.5707288f);
    float s;
    asm("sqrt.approx.f32 %0, %1;" : "=f"(s) : "f"(1.0f - ax));
    float r = s * p;
    return x >= 0.f ? r : 3.14159265358979f - r;
}

// ---------------------------------------------------------------------------
static constexpr int TOTAL_ROWS = 32 * 16384;        // 524288
static constexpr int TILE_ROWS  = 256;
static constexpr int TILES      = TOTAL_ROWS / TILE_ROWS;  // 2048
static constexpr float INV_PI   = 0.3183098861837907f;
static constexpr float INV_2PI  = 0.15915494309189535f;

// SMEM word (uint32) map
static constexpr int PB1 = 0;                   // 128
static constexpr int PB2 = 128;                 // 128
static constexpr int PB3 = 256;                 // 64
static constexpr int GT1 = 320;                 // 256: {g0,g1,t0,t1} per col-pair
static constexpr int GT2 = 576;                 // 256
static constexpr int PCRT = 832, PSRT = 848, PRP = 864;
static constexpr int W1F = 896;                 // 8 pairs  * 128 words = 1024
static constexpr int W2F = 1920;                // 64 pairs * 128 = 8192
static constexpr int W3F = 10112;               // 32 pairs * 128 = 4096
static constexpr int F2  = 14208;               // 256 rows * 8 half2-words = 2048
static constexpr int SMEM_WORDS = 16256;
static constexpr int SMEM_BYTES = SMEM_WORDS * 4;  // 65024

// Paired B packing for m16n8k16 f16 (B col-major K x N):
// pair covers n in [16np,16np+16): sub=0 -> cols 16np..+7, sub=1 -> +8..+15.
// lane l=(n&7)*4+((k>>1)&3) reads uint4 at (pair*128 + l*4):
//   .x/.y = b-frag words of block sub=0, .z/.w = block sub=1.
DEVINL void pack_pair(__half* hw, int base_words, int pair, int sub,
                      int kk, int nn, float v) {
    int lane = (nn << 2) | ((kk >> 1) & 3);
    int s    = kk >> 3;
    int pos  = kk & 1;
    hw[(base_words + pair * 128 + lane * 4 + sub * 2 + s) * 2 + pos] = __float2half_rn(v);
}

// Init a [NT][4] accumulator block from a bias vector (bias becomes the MMA
// C-operand: D = A*B + bias). Rows gid and gid+8 share the same columns.
template <int NT>
DEVINL void acc_bias_init(float (*accm)[4], const float* bS, int tig) {
#pragma unroll
    for (int nt = 0; nt < NT; nt++) {
        uint64_t b01 = *reinterpret_cast<const uint64_t*>(bS + 8 * nt + 2 * tig);
        upk2(b01, accm[nt][0], accm[nt][1]);
        accm[nt][2] = accm[nt][0];
        accm[nt][3] = accm[nt][1];
    }
}

// LN stats (bias already inside acc): packed partials, 2-stage shuffle.
DEVINL void ln_stats(const float (*accm)[4], int tig,
                     uint64_t& rs0p, uint64_t& be0p, uint64_t& rs1p, uint64_t& be1p) {
    uint64_t sp00 = 0, sp01 = 0, qp00 = 0, qp01 = 0;   // row gid
    uint64_t sp10 = 0, sp11 = 0, qp10 = 0, qp11 = 0;   // row gid+8
#pragma unroll
    for (int nt = 0; nt < 16; nt++) {
        uint64_t x01 = pk2(accm[nt][0], accm[nt][1]);
        uint64_t x23 = pk2(accm[nt][2], accm[nt][3]);
        if (nt & 1) {
            sp01 = add2(sp01, x01); qp01 = fma2(x01, x01, qp01);
            sp11 = add2(sp11, x23); qp11 = fma2(x23, x23, qp11);
        } else {
            sp00 = add2(sp00, x01); qp00 = fma2(x01, x01, qp00);
            sp10 = add2(sp10, x23); qp10 = fma2(x23, x23, qp10);
        }
    }
    float lo, hi;
    upk2(add2(sp00, sp01), lo, hi); float s0 = lo + hi;
    upk2(add2(qp00, qp01), lo, hi); float q0 = lo + hi;
    upk2(add2(sp10, sp11), lo, hi); float s1 = lo + hi;
    upk2(add2(qp10, qp11), lo, hi); float q1 = lo + hi;
    s0 += __shfl_xor_sync(0xffffffffu, s0, 1);
    s0 += __shfl_xor_sync(0xffffffffu, s0, 2);
    q0 += __shfl_xor_sync(0xffffffffu, q0, 1);
    q0 += __shfl_xor_sync(0xffffffffu, q0, 2);
    s1 += __shfl_xor_sync(0xffffffffu, s1, 1);
    s1 += __shfl_xor_sync(0xffffffffu, s1, 2);
    q1 += __shfl_xor_sync(0xffffffffu, q1, 1);
    q1 += __shfl_xor_sync(0xffffffffu, q1, 2);
    float mu0 = s0 * 0.0078125f;
    float mu1 = s1 * 0.0078125f;
    float rs0 = rsqrtf(fmaf(-mu0, mu0, q0 * 0.0078125f) + 1e-5f);
    float rs1 = rsqrtf(fmaf(-mu1, mu1, q1 * 0.0078125f) + 1e-5f);
    rs0p = pk2(rs0, rs0); be0p = pk2(-mu0 * rs0, -mu0 * rs0);
    rs1p = pk2(rs1, rs1); be1p = pk2(-mu1 * rs1, -mu1 * rs1);
}

// Normalize + relu + fp16-pack the 4 A-frag words for one kt.
// gtS: interleaved {g0,g1,t0,t1} per column pair -> one LDS.128 per block.
DEVINL void pack_kt(const float (*accm)[4], int kt, int tig, const float* gtS,
                    uint64_t rs0p, uint64_t be0p, uint64_t rs1p, uint64_t be1p,
                    __half2 hz, uint32_t* frag) {
    int cA = 16 * kt + 2 * tig;
    float4 gtA = *reinterpret_cast<const float4*>(gtS + cA * 2);
    float4 gtB = *reinterpret_cast<const float4*>(gtS + (cA + 8) * 2);
    uint64_t gA = pk2(gtA.x, gtA.y), tA = pk2(gtA.z, gtA.w);
    uint64_t gB = pk2(gtB.x, gtB.y), tB = pk2(gtB.z, gtB.w);
    frag[0] = h2_from_pk(fma2(fma2(pk2(accm[2*kt][0],   accm[2*kt][1]),   rs0p, be0p), gA, tA), hz);
    frag[1] = h2_from_pk(fma2(fma2(pk2(accm[2*kt][2],   accm[2*kt][3]),   rs1p, be1p), gA, tA), hz);
    frag[2] = h2_from_pk(fma2(fma2(pk2(accm[2*kt+1][0], accm[2*kt+1][1]), rs0p, be0p), gB, tB), hz);
    frag[3] = h2_from_pk(fma2(fma2(pk2(accm[2*kt+1][2], accm[2*kt+1][3]), rs1p, be1p), gB, tB), hz);
}

__global__ void __launch_bounds__(256, 1)
geo_trunk_kernel(const float* __restrict__ coords,
                 const float* __restrict__ ref_theta, const float* __restrict__ ref_phi,
                 const float* __restrict__ W1, const float* __restrict__ b1,
                 const float* __restrict__ g1, const float* __restrict__ bt1,
                 const float* __restrict__ W2, const float* __restrict__ b2,
                 const float* __restrict__ g2, const float* __restrict__ bt2,
                 const float* __restrict__ W3, const float* __restrict__ b3,
                 float* __restrict__ out) {
    extern __shared__ float sf[];
    uint32_t* su = reinterpret_cast<uint32_t*>(sf);
    __half*   hw = reinterpret_cast<__half*>(sf);

    const int tid  = threadIdx.x;
    const int lane = tid & 31;
    const int gid  = lane >> 2;
    const int tig  = lane & 3;
    const int wrow = (tid >> 5) * 32;   // CTA-local row base of this warp

    // ---- one-time setup ----
    for (int t = tid; t < 16 * 128; t += 256) {        // W1 (zero-pad k>=13)
        int k = t >> 7, n = t & 127;
        pack_pair(hw, W1F, n >> 4, (n >> 3) & 1, k & 15, n & 7,
                  k < 13 ? W1[k * 128 + n] : 0.0f);
    }
    for (int t = tid; t < 128 * 128; t += 256) {       // W2
        int k = t >> 7, n = t & 127;
        pack_pair(hw, W2F, (k >> 4) * 8 + (n >> 4), (n >> 3) & 1, k & 15, n & 7, W2[t]);
    }
    for (int t = tid; t < 128 * 64; t += 256) {        // W3
        int k = t >> 6, n = t & 63;
        pack_pair(hw, W3F, (k >> 4) * 4 + (n >> 4), (n >> 3) & 1, k & 15, n & 7, W3[t]);
    }
    if (tid < 128) {
        sf[PB1 + tid] = b1[tid];
        sf[PB2 + tid] = b2[tid];
        if (tid < 64) sf[PB3 + tid] = b3[tid];
        // interleaved {g0,g1,t0,t1} per column pair
        int p = tid >> 1, w = tid & 1;
        sf[GT1 + p * 4 + w]     = g1[tid];
        sf[GT1 + p * 4 + 2 + w] = bt1[tid];
        sf[GT2 + p * 4 + w]     = g2[tid];
        sf[GT2 + p * 4 + 2 + w] = bt2[tid];
        if (tid < 10) {
            float rt = ref_theta[tid];
            sf[PCRT + tid] = cosf(rt);
            sf[PSRT + tid] = sinf(rt);
            sf[PRP + tid]  = ref_phi[tid];
        }
    }
    __syncthreads();

    const float* bS1 = sf + PB1; const float* bS2 = sf + PB2; const float* bS3 = sf + PB3;
    const float* gtS1 = sf + GT1; const float* gtS2 = sf + GT2;
    const float* crt = sf + PCRT; const float* srt = sf + PSRT; const float* rp = sf + PRP;
    const float2* coords2 = reinterpret_cast<const float2*>(coords);
    const __half2 hz = __float2half2_rn(0.f);

    // prefetch first tile's coords
    float2 tp = coords2[blockIdx.x * TILE_ROWS + tid];

    for (int tile = blockIdx.x; tile < TILES; tile += gridDim.x) {
        // ============== features: 1 row / thread ==============
        {
            float th = tp.x, ph = tp.y;
            float st, ct;
            __sincosf(th, &st, &ct);
            float f[16];
#pragma unroll
            for (int r = 0; r < 10; r++) {
                float cd = fmaf(st * srt[r], __cosf(ph - rp[r]), ct * crt[r]);
                cd = fminf(1.0f, fmaxf(-1.0f, cd));
                f[r] = fast_acos(cd) * INV_PI;
            }
            f[10] = th * INV_PI;
            f[11] = ph * INV_2PI;
            f[12] = 1.0f;
            f[13] = 0.f; f[14] = 0.f; f[15] = 0.f;
            const int sw = ((tid >> 2) & 1) << 2;  // feat swizzle bit
#pragma unroll
            for (int i = 0; i < 8; i++) {
                __half2 h = __floats2half2_rn(f[2 * i], f[2 * i + 1]);
                su[F2 + tid * 8 + (i ^ sw)] = *reinterpret_cast<uint32_t*>(&h);
            }
        }
        // prefetch next tile's coords (flies under the MMA phases)
        {
            int ntile = tile + gridDim.x;
            if (ntile < TILES) tp = coords2[ntile * TILE_ROWS + tid];
        }
        __syncwarp();

        float    acc[2][16][4];
        uint32_t ha[2][8][4];   // activation A-fragments (layer1 -> layer2)

        // ============== layer 1: feats[256x16] @ W1 + b1 (C = bias) ==============
        acc_bias_init<16>(acc[0], bS1, tig);
        acc_bias_init<16>(acc[1], bS1, tig);
        {
            uint32_t a[2][4];
#pragma unroll
            for (int mt = 0; mt < 2; mt++) {
                int r0 = wrow + mt * 16 + gid;
                int s0 = ((r0 >> 2) & 1) << 2;
                a[mt][0] = su[F2 + r0 * 8       + (tig ^ s0)];
                a[mt][1] = su[F2 + (r0 + 8) * 8 + (tig ^ s0)];
                a[mt][2] = su[F2 + r0 * 8       + ((tig + 4) ^ s0)];
                a[mt][3] = su[F2 + (r0 + 8) * 8 + ((tig + 4) ^ s0)];
            }
#pragma unroll
            for (int p = 0; p < 8; p++) {
                uint4 bv = *reinterpret_cast<const uint4*>(su + W1F + p * 128 + lane * 4);
                uint32_t b0[2] = {bv.x, bv.y};
                uint32_t b1v[2] = {bv.z, bv.w};
                mma_f16(acc[0][2 * p],     a[0], b0);
                mma_f16(acc[1][2 * p],     a[1], b0);
                mma_f16(acc[0][2 * p + 1], a[0], b1v);
                mma_f16(acc[1][2 * p + 1], a[1], b1v);
            }
        }

        // ============== LN1 epilogue -> ha (both stats chains overlap) ==============
        {
            uint64_t rs0p0, be0p0, rs1p0, be1p0;
            uint64_t rs0p1, be0p1, rs1p1, be1p1;
            ln_stats(acc[0], tig, rs0p0, be0p0, rs1p0, be1p0);
            ln_stats(acc[1], tig, rs0p1, be0p1, rs1p1, be1p1);
#pragma unroll
            for (int kt = 0; kt < 8; kt++) {
                pack_kt(acc[0], kt, tig, gtS1, rs0p0, be0p0, rs1p0, be1p0, hz, ha[0][kt]);
                pack_kt(acc[1], kt, tig, gtS1, rs0p1, be0p1, rs1p1, be1p1, hz, ha[1][kt]);
            }
        }

        // ============== layer 2: h1 @ W2 + b2 (C = bias) ==============
        acc_bias_init<16>(acc[0], bS2, tig);
        acc_bias_init<16>(acc[1], bS2, tig);
#pragma unroll
        for (int kt = 0; kt < 8; kt++) {
#pragma unroll
            for (int p = 0; p < 8; p++) {
                uint4 bv = *reinterpret_cast<const uint4*>(su + W2F + (kt * 8 + p) * 128 + lane * 4);
                uint32_t b0[2] = {bv.x, bv.y};
                uint32_t b1v[2] = {bv.z, bv.w};
                mma_f16(acc[0][2 * p],     ha[0][kt], b0);
                mma_f16(acc[1][2 * p],     ha[1][kt], b0);
                mma_f16(acc[0][2 * p + 1], ha[0][kt], b1v);
                mma_f16(acc[1][2 * p + 1], ha[1][kt], b1v);
            }
        }

        // ============== LN2 epilogue FUSED with layer 3 (C = b3) ==============
        float a3[2][8][4];
        acc_bias_init<8>(a3[0], bS3, tig);
        acc_bias_init<8>(a3[1], bS3, tig);
        {
            uint64_t rs0p0, be0p0, rs1p0, be1p0;
            uint64_t rs0p1, be0p1, rs1p1, be1p1;
            ln_stats(acc[0], tig, rs0p0, be0p0, rs1p0, be1p0);
            ln_stats(acc[1], tig, rs0p1, be0p1, rs1p1, be1p1);
#pragma unroll
            for (int kt = 0; kt < 8; kt++) {
                uint32_t hb0[4], hb1[4];
                pack_kt(acc[0], kt, tig, gtS2, rs0p0, be0p0, rs1p0, be1p0, hz, hb0);
                pack_kt(acc[1], kt, tig, gtS2, rs0p1, be0p1, rs1p1, be1p1, hz, hb1);
#pragma unroll
                for (int p = 0; p < 4; p++) {
                    uint4 bv = *reinterpret_cast<const uint4*>(su + W3F + (kt * 4 + p) * 128 + lane * 4);
                    uint32_t b0[2] = {bv.x, bv.y};
                    uint32_t b1v[2] = {bv.z, bv.w};
                    mma_f16(a3[0][2 * p],     hb0, b0);
                    mma_f16(a3[1][2 * p],     hb1, b0);
                    mma_f16(a3[0][2 * p + 1], hb0, b1v);
                    mma_f16(a3[1][2 * p + 1], hb1, b1v);
                }
            }
        }

        // ============== store (bias already in a3) ==============
        {
            const int rowg = tile * TILE_ROWS + wrow;
#pragma unroll
            for (int mt = 0; mt < 2; mt++) {
                int r0 = rowg + mt * 16 + gid, r1 = r0 + 8;
#pragma unroll
                for (int nt = 0; nt < 8; nt++) {
                    int c0 = 8 * nt + 2 * tig;
                    uint64_t v0 = pk2(a3[mt][nt][0], a3[mt][nt][1]);
                    uint64_t v1 = pk2(a3[mt][nt][2], a3[mt][nt][3]);
                    *reinterpret_cast<uint64_t*>(out + (size_t)r0 * 64 + c0) = v0;
                    *reinterpret_cast<uint64_t*>(out + (size_t)r1 * 64 + c0) = v1;
                }
            }
        }
    }
}

extern "C" void kernel_launch(void* const* d_in, const int* in_sizes, int n_in,
                              void* d_out, int out_size) {
    (void)in_sizes; (void)n_in; (void)out_size;
    cudaFuncSetAttribute(geo_trunk_kernel, cudaFuncAttributeMaxDynamicSharedMemorySize, SMEM_BYTES);
    geo_trunk_kernel<<<148, 256, SMEM_BYTES>>>(
        (const float*)d_in[0],  // coords
        (const float*)d_in[1],  // ref_theta
        (const float*)d_in[2],  // ref_phi
        (const float*)d_in[3],  // W1
        (const float*)d_in[4],  // b1
        (const float*)d_in[5],  // g1
        (const float*)d_in[6],  // bt1
        (const float*)d_in[7],  // W2
        (const float*)d_in[8],  // b2
        (const float*)d_in[9],  // g2
        (const float*)d_in[10], // bt2
        (const float*)d_in[11], // W3
        (const float*)d_in[12], // b3
        (float*)d_out);
}